// round 5
// baseline (speedup 1.0000x reference)
#include <cuda_runtime.h>
#include <cuda_bf16.h>
#include <cstdint>

#define CC   128
#define HH   2
#define HC   256
#define NMAX 100000
#define EMAX 1600000

// ---------------- device scratch (static, no allocation) ----------------
__device__ float g_q[(size_t)NMAX * HC];         // normalized qs fp32
__device__ float g_k[(size_t)NMAX * HC];         // normalized ks fp32
__device__ __nv_bfloat16 g_q16[(size_t)NMAX * HC];
__device__ __nv_bfloat16 g_k16[(size_t)NMAX * HC];
__device__ __nv_bfloat16 g_tA16[(size_t)NMAX * HC];  // term ping (bf16)
__device__ __nv_bfloat16 g_tB16[(size_t)NMAX * HC];  // term pong (bf16)
__device__ float g_deginv[NMAX];
__device__ int   g_deg[NMAX];
__device__ int   g_csroff[NMAX + 1];
__device__ int   g_csrcur[NMAX];
__device__ int   g_csrrow[EMAX];
__device__ float g_den[NMAX * HH];
__device__ float g_kvs[HH * CC * CC];
__device__ float g_vssum[HH * CC];
__device__ float g_kssum[HH * CC];
__device__ int   g_is64;

// ---------------- helpers ----------------
__device__ __forceinline__ uint32_t f2tf(float x) {
    uint32_t r;
    asm("cvt.rna.tf32.f32 %0, %1;" : "=r"(r) : "f"(x));
    return r;
}
__device__ __forceinline__ uint32_t packbf(float lo, float hi) {
    __nv_bfloat162 h2 = __floats2bfloat162_rn(lo, hi);
    return *reinterpret_cast<uint32_t*>(&h2);
}
__device__ __forceinline__ float2 unpackbf(uint32_t u) {
    __nv_bfloat162 h2 = *reinterpret_cast<__nv_bfloat162*>(&u);
    return __bfloat1622float2(h2);
}

__device__ __forceinline__ void mma16(float* c, uint32_t a0, uint32_t a1, uint32_t a2,
                                      uint32_t a3, uint32_t b0, uint32_t b1) {
    asm volatile(
        "mma.sync.aligned.m16n8k16.row.col.f32.bf16.bf16.f32 "
        "{%0,%1,%2,%3},{%4,%5,%6,%7},{%8,%9},{%0,%1,%2,%3};"
        : "+f"(c[0]), "+f"(c[1]), "+f"(c[2]), "+f"(c[3])
        : "r"(a0), "r"(a1), "r"(a2), "r"(a3), "r"(b0), "r"(b1));
}

// tf32 m16n8k8 over a 16-deep k tile (k-major [16][128]) -- used by tf32 GEMMs
__device__ __forceinline__ void ktile_mma(const uint32_t (*As)[128], const uint32_t (*Bs)[128],
                                          int m0, int n0, int lane, float acc[4][4][4]) {
#pragma unroll
    for (int ks = 0; ks < 2; ks++) {
        int ar = ks * 8 + (lane & 3);
        int ac = lane >> 2;
        uint32_t a[4][4], b[4][2];
#pragma unroll
        for (int mt = 0; mt < 4; mt++) {
            int m = m0 + mt * 16 + ac;
            a[mt][0] = As[ar][m];
            a[mt][1] = As[ar][m + 8];
            a[mt][2] = As[ar + 4][m];
            a[mt][3] = As[ar + 4][m + 8];
        }
#pragma unroll
        for (int nt = 0; nt < 4; nt++) {
            int nn = n0 + nt * 8 + ac;
            b[nt][0] = Bs[ar][nn];
            b[nt][1] = Bs[ar + 4][nn];
        }
#pragma unroll
        for (int mt = 0; mt < 4; mt++)
#pragma unroll
            for (int nt = 0; nt < 4; nt++)
                asm volatile(
                    "mma.sync.aligned.m16n8k8.row.col.f32.tf32.tf32.f32 "
                    "{%0,%1,%2,%3},{%4,%5,%6,%7},{%8,%9},{%0,%1,%2,%3};"
                    : "+f"(acc[mt][nt][0]), "+f"(acc[mt][nt][1]),
                      "+f"(acc[mt][nt][2]), "+f"(acc[mt][nt][3])
                    : "r"(a[mt][0]), "r"(a[mt][1]), "r"(a[mt][2]), "r"(a[mt][3]),
                      "r"(b[nt][0]), "r"(b[nt][1]));
    }
}

// bf16 m16n8k16, smem pair-packed along k: S[k2][m], stride 132 (kvs_reduce)
__device__ __forceinline__ void ktile_mma16(const uint32_t (*As)[132], const uint32_t (*Bs)[132],
                                            int m0, int n0, int lane, float acc[4][4][4], int ksteps) {
    for (int ks = 0; ks < ksteps; ks++) {
        int ar = ks * 8 + (lane & 3);
        int ac = lane >> 2;
        uint32_t a[4][4], b[4][2];
#pragma unroll
        for (int mt = 0; mt < 4; mt++) {
            int m = m0 + mt * 16 + ac;
            a[mt][0] = As[ar][m];
            a[mt][1] = As[ar][m + 8];
            a[mt][2] = As[ar + 4][m];
            a[mt][3] = As[ar + 4][m + 8];
        }
#pragma unroll
        for (int nt = 0; nt < 4; nt++) {
            int nn = n0 + nt * 8 + ac;
            b[nt][0] = Bs[ar][nn];
            b[nt][1] = Bs[ar + 4][nn];
        }
#pragma unroll
        for (int mt = 0; mt < 4; mt++)
#pragma unroll
            for (int nt = 0; nt < 4; nt++)
                mma16(acc[mt][nt], a[mt][0], a[mt][1], a[mt][2], a[mt][3], b[nt][0], b[nt][1]);
    }
}

// ---------------- edge dtype detection ----------------
__global__ void detect_dtype_kernel(const int* __restrict__ ei32, int twoE) {
    __shared__ int nz;
    if (threadIdx.x == 0) nz = 0;
    __syncthreads();
    int samples = min(1024, twoE / 2);
    int local = 0;
    for (int i = threadIdx.x; i < samples; i += blockDim.x)
        if (ei32[2 * i + 1] != 0) local++;
    if (local) atomicAdd(&nz, local);
    __syncthreads();
    if (threadIdx.x == 0) g_is64 = (nz == 0) ? 1 : 0;
}

__device__ __forceinline__ int edge_col(const void* ei, int E, int e) {
    if (g_is64) return (int)((const long long*)ei)[(size_t)E + e];
    return ((const int*)ei)[E + e];
}
__device__ __forceinline__ int edge_row(const void* ei, int E, int e) {
    if (g_is64) return (int)((const long long*)ei)[e];
    return ((const int*)ei)[e];
}

// ---------------- edge prep ----------------
__global__ void edge_deg_kernel(const void* __restrict__ ei, int E) {
    int e = blockIdx.x * blockDim.x + threadIdx.x;
    if (e < E) atomicAdd(&g_deg[edge_col(ei, E, e)], 1);
}

__global__ void scan_kernel(int n, int E) {
    __shared__ int sh[1024];
    __shared__ int carrySh;
    if (threadIdx.x == 0) carrySh = 0;
    __syncthreads();
    for (int base = 0; base < n; base += 1024) {
        int i = base + threadIdx.x;
        int v = (i < n) ? g_deg[i] : 0;
        sh[threadIdx.x] = v;
        __syncthreads();
        for (int off = 1; off < 1024; off <<= 1) {
            int t = (threadIdx.x >= off) ? sh[threadIdx.x - off] : 0;
            __syncthreads();
            sh[threadIdx.x] += t;
            __syncthreads();
        }
        int excl = sh[threadIdx.x] - v + carrySh;
        if (i < n) {
            g_csroff[i] = excl;
            g_csrcur[i] = excl;
            g_deginv[i] = (v > 0) ? 1.0f / (float)v : 0.0f;
        }
        __syncthreads();
        if (threadIdx.x == 0) carrySh += sh[1023];
        __syncthreads();
    }
    if (threadIdx.x == 0) g_csroff[n] = E;
}

__global__ void csr_scatter_kernel(const void* __restrict__ ei, int E) {
    int e = blockIdx.x * blockDim.x + threadIdx.x;
    if (e < E) {
        int c = edge_col(ei, E, e);
        int pos = atomicAdd(&g_csrcur[c], 1);
        g_csrrow[pos] = edge_row(ei, E, e);
    }
}

// ---------------- iter-1 GCN gather from fp32 x: nxt = 0.5*deginv*sum x[src], dup heads ----------------
__global__ void gcn_gather_x_kernel(const float* __restrict__ x, __nv_bfloat16* __restrict__ nxt, int n) {
    int gw = (blockIdx.x * blockDim.x + threadIdx.x) >> 5;
    int lane = threadIdx.x & 31;
    if (gw >= n) return;
    int beg = g_csroff[gw], end = g_csroff[gw + 1];
    float s = 0.5f * g_deginv[gw];
    float4 a = make_float4(0, 0, 0, 0);
    int e = beg;
    for (; e + 4 <= end; e += 4) {
        int s0 = g_csrrow[e], s1 = g_csrrow[e + 1], s2 = g_csrrow[e + 2], s3 = g_csrrow[e + 3];
        float4 v0 = ((const float4*)(x + (size_t)s0 * 128))[lane];
        float4 v1 = ((const float4*)(x + (size_t)s1 * 128))[lane];
        float4 v2 = ((const float4*)(x + (size_t)s2 * 128))[lane];
        float4 v3 = ((const float4*)(x + (size_t)s3 * 128))[lane];
        a.x += (v0.x + v1.x) + (v2.x + v3.x);
        a.y += (v0.y + v1.y) + (v2.y + v3.y);
        a.z += (v0.z + v1.z) + (v2.z + v3.z);
        a.w += (v0.w + v1.w) + (v2.w + v3.w);
    }
    for (; e < end; e++) {
        float4 v0 = ((const float4*)(x + (size_t)g_csrrow[e] * 128))[lane];
        a.x += v0.x; a.y += v0.y; a.z += v0.z; a.w += v0.w;
    }
    uint2 o;
    o.x = packbf(s * a.x, s * a.y);
    o.y = packbf(s * a.z, s * a.w);
    *(uint2*)(nxt + (size_t)gw * 256 + lane * 4)       = o;
    *(uint2*)(nxt + (size_t)gw * 256 + 128 + lane * 4) = o;
}

// ---------------- q/k projection GEMM (tf32): [N,128] @ [128,512] ----------------
__global__ void __launch_bounds__(256) qk_gemm_kernel(const float* __restrict__ x,
                               const float* __restrict__ Wq, const float* __restrict__ Wqb,
                               const float* __restrict__ Wk, const float* __restrict__ Wkb,
                               int n) {
    __shared__ uint32_t As[16][128];
    __shared__ uint32_t Bs[16][128];
    int t = threadIdx.x;
    int lane = t & 31, wid = t >> 5;
    int m0 = (wid & 1) * 64, n0 = (wid >> 1) * 32;
    int bm0 = blockIdx.x * 128;
    int by = blockIdx.y;
    const float* B   = (by < 2) ? Wq  : Wk;
    const float* bia = (by < 2) ? Wqb : Wkb;
    float*       dst = (by < 2) ? g_q : g_k;
    int coff = (by & 1) * 128;
    int am = t >> 1, akq = (t & 1) * 8;
    int bk = t >> 4, bnq = (t & 15) * 8;
    float acc[4][4][4];
#pragma unroll
    for (int i = 0; i < 4; i++)
#pragma unroll
        for (int j = 0; j < 4; j++)
#pragma unroll
            for (int r = 0; r < 4; r++) acc[i][j][r] = 0.f;

    for (int k0 = 0; k0 < 128; k0 += 16) {
        float4 a0 = make_float4(0, 0, 0, 0), a1 = a0;
        int row = bm0 + am;
        if (row < n) {
            const float4* ap = (const float4*)(x + (size_t)row * 128 + k0 + akq);
            a0 = ap[0]; a1 = ap[1];
        }
        const float4* bp = (const float4*)(B + (size_t)(k0 + bk) * 256 + coff + bnq);
        float4 b0 = bp[0], b1 = bp[1];
        __syncthreads();
        As[akq + 0][am] = f2tf(a0.x); As[akq + 1][am] = f2tf(a0.y);
        As[akq + 2][am] = f2tf(a0.z); As[akq + 3][am] = f2tf(a0.w);
        As[akq + 4][am] = f2tf(a1.x); As[akq + 5][am] = f2tf(a1.y);
        As[akq + 6][am] = f2tf(a1.z); As[akq + 7][am] = f2tf(a1.w);
        Bs[bk][bnq + 0] = f2tf(b0.x); Bs[bk][bnq + 1] = f2tf(b0.y);
        Bs[bk][bnq + 2] = f2tf(b0.z); Bs[bk][bnq + 3] = f2tf(b0.w);
        Bs[bk][bnq + 4] = f2tf(b1.x); Bs[bk][bnq + 5] = f2tf(b1.y);
        Bs[bk][bnq + 6] = f2tf(b1.z); Bs[bk][bnq + 7] = f2tf(b1.w);
        __syncthreads();
        ktile_mma(As, Bs, m0, n0, lane, acc);
    }
#pragma unroll
    for (int mt = 0; mt < 4; mt++) {
        int row = bm0 + m0 + mt * 16 + (lane >> 2);
#pragma unroll
        for (int nt = 0; nt < 4; nt++) {
            int col = coff + n0 + nt * 8 + 2 * (lane & 3);
            float bx = bia[col], by2 = bia[col + 1];
            if (row < n) {
                float2 v = make_float2(acc[mt][nt][0] + bx, acc[mt][nt][1] + by2);
                *(float2*)&dst[(size_t)row * 256 + col] = v;
            }
            if (row + 8 < n) {
                float2 v = make_float2(acc[mt][nt][2] + bx, acc[mt][nt][3] + by2);
                *(float2*)&dst[(size_t)(row + 8) * 256 + col] = v;
            }
        }
    }
}

// ---------------- normalize (fp32) + write bf16 copies ----------------
__global__ void normalize_kernel(int n) {
    int gw = (blockIdx.x * blockDim.x + threadIdx.x) >> 5;
    int lane = threadIdx.x & 31;
    if (gw >= n * 4) return;
    int node = gw >> 2, sel = gw & 3;
    size_t off = (size_t)node * 256 + (sel & 1) * 128;
    float* base = ((sel < 2) ? g_q : g_k) + off;
    __nv_bfloat16* b16 = ((sel < 2) ? g_q16 : g_k16) + off;
    float4 v = ((float4*)base)[lane];
    float ss = v.x * v.x + v.y * v.y + v.z * v.z + v.w * v.w;
#pragma unroll
    for (int o = 16; o; o >>= 1) ss += __shfl_xor_sync(0xffffffffu, ss, o);
    float inv = rsqrtf(ss);
    v.x *= inv; v.y *= inv; v.z *= inv; v.w *= inv;
    ((float4*)base)[lane] = v;
    uint2 u;
    u.x = packbf(v.x, v.y);
    u.y = packbf(v.z, v.w);
    *(uint2*)(b16 + lane * 4) = u;
}

// ---------------- ks_sum (loop-invariant, fp32) ----------------
__global__ void kssum_kernel(int n) {
    int col = threadIdx.x;  // 0..255
    int start = blockIdx.x * 512;
    int end = min(start + 512, n);
    float s = 0.f;
    for (int node = start; node < end; node++) s += g_k[(size_t)node * 256 + col];
    atomicAdd(&g_kssum[col], s);
}

// ---------------- den = qs . ks_sum + n (loop-invariant, fp32) ----------------
__global__ void den_kernel(int n) {
    int gw = (blockIdx.x * blockDim.x + threadIdx.x) >> 5;
    int lane = threadIdx.x & 31;
    if (gw >= n * 2) return;
    int node = gw >> 1, h = gw & 1;
    float4 qv = ((const float4*)(g_q + (size_t)node * 256 + h * 128))[lane];
    float4 kv = ((const float4*)(g_kssum + h * 128))[lane];
    float d = qv.x * kv.x + qv.y * kv.y + qv.z * kv.z + qv.w * kv.w;
#pragma unroll
    for (int o = 16; o; o >>= 1) d += __shfl_xor_sync(0xffffffffu, d, o);
    if (lane == 0) g_den[node * 2 + h] = d + (float)n;
}

// ---------------- term0 = broadcast x over heads (bf16) ----------------
__global__ void broadcast_kernel(const float* __restrict__ x, int n) {
    int idx = blockIdx.x * blockDim.x + threadIdx.x;
    if (idx < n * 256) {
        int node = idx >> 8;
        int c = idx & 127;
        g_tA16[idx] = __float2bfloat16(x[(size_t)node * 128 + c]);
    }
}

// ---------------- out init (tf32): 0.5*(x @ (Wo[h0,k0]+Wo[h1,k0]) + b) ----------------
__global__ void __launch_bounds__(256) out_init_kernel(const float* __restrict__ x, const float* __restrict__ Wo,
                                const float* __restrict__ Wob, float* __restrict__ out, int n) {
    __shared__ uint32_t As[16][128];
    __shared__ uint32_t Bs[16][128];
    int t = threadIdx.x;
    int lane = t & 31, wid = t >> 5;
    int m0 = (wid & 1) * 64, n0 = (wid >> 1) * 32;
    int bm0 = blockIdx.x * 128;
    int am = t >> 1, akq = (t & 1) * 8;
    int bk = t >> 4, bnq = (t & 15) * 8;
    float acc[4][4][4];
#pragma unroll
    for (int i = 0; i < 4; i++)
#pragma unroll
        for (int j = 0; j < 4; j++)
#pragma unroll
            for (int r = 0; r < 4; r++) acc[i][j][r] = 0.f;

    for (int k0 = 0; k0 < 128; k0 += 16) {
        float4 a0 = make_float4(0, 0, 0, 0), a1 = a0;
        int row = bm0 + am;
        if (row < n) {
            const float4* ap = (const float4*)(x + (size_t)row * 128 + k0 + akq);
            a0 = ap[0]; a1 = ap[1];
        }
        int wr = k0 + bk;
        const float4* p0 = (const float4*)(Wo + (size_t)wr * 128 + bnq);
        const float4* p1 = (const float4*)(Wo + (size_t)(640 + wr) * 128 + bnq);
        float4 u0 = p0[0], u1 = p0[1], v0 = p1[0], v1 = p1[1];
        __syncthreads();
        As[akq + 0][am] = f2tf(a0.x); As[akq + 1][am] = f2tf(a0.y);
        As[akq + 2][am] = f2tf(a0.z); As[akq + 3][am] = f2tf(a0.w);
        As[akq + 4][am] = f2tf(a1.x); As[akq + 5][am] = f2tf(a1.y);
        As[akq + 6][am] = f2tf(a1.z); As[akq + 7][am] = f2tf(a1.w);
        Bs[bk][bnq + 0] = f2tf(u0.x + v0.x); Bs[bk][bnq + 1] = f2tf(u0.y + v0.y);
        Bs[bk][bnq + 2] = f2tf(u0.z + v0.z); Bs[bk][bnq + 3] = f2tf(u0.w + v0.w);
        Bs[bk][bnq + 4] = f2tf(u1.x + v1.x); Bs[bk][bnq + 5] = f2tf(u1.y + v1.y);
        Bs[bk][bnq + 6] = f2tf(u1.z + v1.z); Bs[bk][bnq + 7] = f2tf(u1.w + v1.w);
        __syncthreads();
        ktile_mma(As, Bs, m0, n0, lane, acc);
    }
#pragma unroll
    for (int mt = 0; mt < 4; mt++) {
        int row = bm0 + m0 + mt * 16 + (lane >> 2);
#pragma unroll
        for (int nt = 0; nt < 4; nt++) {
            int col = n0 + nt * 8 + 2 * (lane & 3);
            float bx = Wob[col], by2 = Wob[col + 1];
            if (row < n) {
                float2 v = make_float2(0.5f * (acc[mt][nt][0] + bx), 0.5f * (acc[mt][nt][1] + by2));
                *(float2*)&out[(size_t)row * 128 + col] = v;
            }
            if (row + 8 < n) {
                float2 v = make_float2(0.5f * (acc[mt][nt][2] + bx), 0.5f * (acc[mt][nt][3] + by2));
                *(float2*)&out[(size_t)(row + 8) * 128 + col] = v;
            }
        }
    }
}

// ---------------- kvs[h] += ks^T @ prev (bf16 mma) ; vs_sum (fp32) ----------------
__global__ void __launch_bounds__(256) kvs_reduce_kernel(const __nv_bfloat16* __restrict__ prev, int n) {
    int h = blockIdx.y;
    int c0 = blockIdx.x * 1024;
    int c1 = min(c0 + 1024, n);
    __shared__ uint32_t ksS[16][132];
    __shared__ uint32_t pvS[16][132];
    int t = threadIdx.x;
    int lane = t & 31, wid = t >> 5;
    int m0 = (wid & 1) * 64, n0 = (wid >> 1) * 32;
    float acc[4][4][4];
#pragma unroll
    for (int i = 0; i < 4; i++)
#pragma unroll
        for (int j = 0; j < 4; j++)
#pragma unroll
            for (int r = 0; r < 4; r++) acc[i][j][r] = 0.f;
    float colsum = 0.f;
    int myc = t & 127, hb = (t >> 7) * 8;

    for (int s = c0; s < c1; s += 32) {
        __syncthreads();
#pragma unroll
        for (int i = 0; i < 4; i++) {
            int u = t + 256 * i;
            int nn = u >> 6, m2 = u & 63;
            int nd0 = s + 2 * nn, nd1 = nd0 + 1;
            uint32_t k0 = 0, k1 = 0, p0 = 0, p1 = 0;
            if (nd0 < c1) {
                k0 = *(const uint32_t*)(g_k16 + (size_t)nd0 * 256 + h * 128 + 2 * m2);
                p0 = *(const uint32_t*)(prev  + (size_t)nd0 * 256 + h * 128 + 2 * m2);
            }
            if (nd1 < c1) {
                k1 = *(const uint32_t*)(g_k16 + (size_t)nd1 * 256 + h * 128 + 2 * m2);
                p1 = *(const uint32_t*)(prev  + (size_t)nd1 * 256 + h * 128 + 2 * m2);
            }
            ksS[nn][2 * m2]     = __byte_perm(k0, k1, 0x5410);
            ksS[nn][2 * m2 + 1] = __byte_perm(k0, k1, 0x7632);
            pvS[nn][2 * m2]     = __byte_perm(p0, p1, 0x5410);
            pvS[nn][2 * m2 + 1] = __byte_perm(p0, p1, 0x7632);
        }
        __syncthreads();
        ktile_mma16(ksS, pvS, m0, n0, lane, acc, 2);
#pragma unroll
        for (int r = 0; r < 8; r++) {
            float2 f = unpackbf(pvS[hb + r][myc]);
            colsum += f.x + f.y;
        }
    }
    atomicAdd(&g_vssum[h * 128 + myc], colsum);
    float* kv = g_kvs + h * 16384;
#pragma unroll
    for (int mt = 0; mt < 4; mt++) {
        int m = m0 + mt * 16 + (lane >> 2);
#pragma unroll
        for (int nt = 0; nt < 4; nt++) {
            int c = n0 + nt * 8 + 2 * (lane & 3);
            atomicAdd(&kv[m * 128 + c],           acc[mt][nt][0]);
            atomicAdd(&kv[m * 128 + c + 1],       acc[mt][nt][1]);
            atomicAdd(&kv[(m + 8) * 128 + c],     acc[mt][nt][2]);
            atomicAdd(&kv[(m + 8) * 128 + c + 1], acc[mt][nt][3]);
        }
    }
}

// ==================== fused per-iteration kernel ====================
// Per 128-row block: (1) gather gcn term into smem Ts (or load pre-gathered on
// first iter), (2) attention GEMM per head + add gcn -> write nxt once,
// (3) out += 0.5 * term @ Wo_slice with A read from Ts in smem.
#define TS_STRIDE 132
#define AQ_STRIDE 20
#define BS_STRIDE 136
#define SM_WORDS  (128 * TS_STRIDE + 128 * AQ_STRIDE + 16 * BS_STRIDE)

__global__ void __launch_bounds__(256) iter_fused_kernel(
    const __nv_bfloat16* __restrict__ prev, __nv_bfloat16* __restrict__ nxt,
    const float* __restrict__ Wo, float* __restrict__ out,
    int n, int ksl, int first) {
    extern __shared__ uint32_t sm[];
    uint32_t (*Ts)[TS_STRIDE] = (uint32_t(*)[TS_STRIDE])sm;
    uint32_t (*Aq)[AQ_STRIDE] = (uint32_t(*)[AQ_STRIDE])(sm + 128 * TS_STRIDE);
    uint32_t (*Bs)[BS_STRIDE] = (uint32_t(*)[BS_STRIDE])(sm + 128 * TS_STRIDE + 128 * AQ_STRIDE);

    int t = threadIdx.x, lane = t & 31, wid = t >> 5;
    int bm0 = blockIdx.x * 128;
    int m0 = (wid & 1) * 64, n0 = (wid >> 1) * 32;

    // ---- phase 1: gcn term tile into Ts ----
    if (first) {
        for (int r = wid; r < 128; r += 8) {
            int row = bm0 + r;
            uint4 v = make_uint4(0, 0, 0, 0);
            if (row < n) v = *(const uint4*)(nxt + (size_t)row * 256 + lane * 8);
            Ts[r][lane * 4 + 0] = v.x; Ts[r][lane * 4 + 1] = v.y;
            Ts[r][lane * 4 + 2] = v.z; Ts[r][lane * 4 + 3] = v.w;
        }
    } else {
        for (int r = wid; r < 128; r += 8) {
            int row = bm0 + r;
            float a[8];
#pragma unroll
            for (int i = 0; i < 8; i++) a[i] = 0.f;
            float s = 0.f;
            if (row < n) {
                int beg = g_csroff[row], end = g_csroff[row + 1];
                s = 0.5f * g_deginv[row];
                int e = beg;
                for (; e + 2 <= end; e += 2) {
                    uint4 v0 = *(const uint4*)(prev + (size_t)g_csrrow[e]     * 256 + lane * 8);
                    uint4 v1 = *(const uint4*)(prev + (size_t)g_csrrow[e + 1] * 256 + lane * 8);
#pragma unroll
                    for (int p = 0; p < 4; p++) {
                        float2 f0 = unpackbf((&v0.x)[p]);
                        float2 f1 = unpackbf((&v1.x)[p]);
                        a[2 * p]     += f0.x + f1.x;
                        a[2 * p + 1] += f0.y + f1.y;
                    }
                }
                if (e < end) {
                    uint4 v0 = *(const uint4*)(prev + (size_t)g_csrrow[e] * 256 + lane * 8);
#pragma unroll
                    for (int p = 0; p < 4; p++) {
                        float2 f0 = unpackbf((&v0.x)[p]);
                        a[2 * p] += f0.x; a[2 * p + 1] += f0.y;
                    }
                }
            }
#pragma unroll
            for (int j = 0; j < 4; j++)
                Ts[r][lane * 4 + j] = packbf(s * a[2 * j], s * a[2 * j + 1]);
        }
    }
    __syncthreads();

    // ---- phase 2: attention per head: acc = q16 @ kvs; term += (acc+vs)/den ----
    for (int h = 0; h < 2; h++) {
        const float* kvp = g_kvs + h * 16384;
        float acc[4][4][4];
#pragma unroll
        for (int i = 0; i < 4; i++)
#pragma unroll
            for (int j = 0; j < 4; j++)
#pragma unroll
                for (int r = 0; r < 4; r++) acc[i][j][r] = 0.f;

        for (int kc = 0; kc < 4; kc++) {  // 32 k-elems (16 pairs) per chunk
            int kb = kc * 32;
            __syncthreads();
            // stage A: q16 rows [128][16 pairs]
#pragma unroll
            for (int i = 0; i < 2; i++) {
                int u = t + 256 * i;           // 0..511
                int r = u >> 2, q4 = u & 3;    // 4 x uint4 per row
                uint4 v = make_uint4(0, 0, 0, 0);
                if (bm0 + r < n)
                    v = *(const uint4*)(g_q16 + (size_t)(bm0 + r) * 256 + h * 128 + kb + q4 * 8);
                Aq[r][q4 * 4 + 0] = v.x; Aq[r][q4 * 4 + 1] = v.y;
                Aq[r][q4 * 4 + 2] = v.z; Aq[r][q4 * 4 + 3] = v.w;
            }
            // stage B: kvs fp32 -> bf16 pairs [16 pairs][128]
#pragma unroll
            for (int i = 0; i < 8; i++) {
                int u = t + 256 * i;           // 0..2047
                int k2 = u >> 7, c = u & 127;
                int kk = kb + 2 * k2;
                Bs[k2][c] = packbf(kvp[kk * 128 + c], kvp[(kk + 1) * 128 + c]);
            }
            __syncthreads();
#pragma unroll
            for (int ks = 0; ks < 2; ks++) {
                int pb = ks * 8 + (lane & 3);
                uint32_t b[4][2];
#pragma unroll
                for (int nt = 0; nt < 4; nt++) {
                    int nn = n0 + nt * 8 + (lane >> 2);
                    b[nt][0] = Bs[pb][nn];
                    b[nt][1] = Bs[pb + 4][nn];
                }
#pragma unroll
                for (int mt = 0; mt < 4; mt++) {
                    int m = m0 + mt * 16 + (lane >> 2);
                    uint32_t a0 = Aq[m][pb], a1 = Aq[m + 8][pb];
                    uint32_t a2 = Aq[m][pb + 4], a3 = Aq[m + 8][pb + 4];
#pragma unroll
                    for (int nt = 0; nt < 4; nt++)
                        mma16(acc[mt][nt], a0, a1, a2, a3, b[nt][0], b[nt][1]);
                }
            }
        }
        // epilogue: term = Ts + (acc + vs)/den ; write Ts (smem) and nxt (gmem)
#pragma unroll
        for (int mt = 0; mt < 4; mt++) {
            int r = m0 + mt * 16 + (lane >> 2);
#pragma unroll
            for (int nt = 0; nt < 4; nt++) {
                int col = n0 + nt * 8 + 2 * (lane & 3);
                int w2 = h * 64 + (col >> 1);
                float vs0 = g_vssum[h * 128 + col], vs1 = g_vssum[h * 128 + col + 1];
                {
                    int row = bm0 + r;
                    float invd = (row < n) ? 1.0f / g_den[row * 2 + h] : 0.f;
                    float2 g = unpackbf(Ts[r][w2]);
                    uint32_t pw = packbf(g.x + (acc[mt][nt][0] + vs0) * invd,
                                         g.y + (acc[mt][nt][1] + vs1) * invd);
                    Ts[r][w2] = pw;
                    if (row < n) *(uint32_t*)(nxt + (size_t)row * 256 + h * 128 + col) = pw;
                }
                {
                    int row = bm0 + r + 8;
                    float invd = (row < n) ? 1.0f / g_den[row * 2 + h] : 0.f;
                    float2 g = unpackbf(Ts[r + 8][w2]);
                    uint32_t pw = packbf(g.x + (acc[mt][nt][2] + vs0) * invd,
                                         g.y + (acc[mt][nt][3] + vs1) * invd);
                    Ts[r + 8][w2] = pw;
                    if (row < n) *(uint32_t*)(nxt + (size_t)row * 256 + h * 128 + col) = pw;
                }
            }
        }
    }
    __syncthreads();

    // ---- phase 3: out += 0.5 * term @ Wo_slice, A direct from Ts ----
    float acc[4][4][4];
#pragma unroll
    for (int i = 0; i < 4; i++)
#pragma unroll
        for (int j = 0; j < 4; j++)
#pragma unroll
            for (int r = 0; r < 4; r++) acc[i][j][r] = 0.f;

    for (int kc = 0; kc < 8; kc++) {  // 32 k-elems per chunk over K=256
        int kb2 = kc * 16;            // pair base into Ts
        __syncthreads();
#pragma unroll
        for (int i = 0; i < 8; i++) {
            int u = t + 256 * i;
            int k2 = u >> 7, c = u & 127;
            int j = kc * 32 + 2 * k2;
            int wrow = ((j >> 7) * 640) + ksl * 128 + (j & 127);
            Bs[k2][c] = packbf(Wo[(size_t)wrow * 128 + c], Wo[(size_t)(wrow + 1) * 128 + c]);
        }
        __syncthreads();
#pragma unroll
        for (int ks = 0; ks < 2; ks++) {
            int pb = ks * 8 + (lane & 3);
            uint32_t b[4][2];
#pragma unroll
            for (int nt = 0; nt < 4; nt++) {
                int nn = n0 + nt * 8 + (lane >> 2);
                b[nt][0] = Bs[pb][nn];
                b[nt][1] = Bs[pb + 4][nn];
            }
#pragma unroll
            for (int mt = 0; mt < 4; mt++) {
                int m = m0 + mt * 16 + (lane >> 2);
                uint32_t a0 = Ts[m][kb2 + pb], a1 = Ts[m + 8][kb2 + pb];
                uint32_t a2 = Ts[m][kb2 + pb + 4], a3 = Ts[m + 8][kb2 + pb + 4];
#pragma unroll
                for (int nt = 0; nt < 4; nt++)
                    mma16(acc[mt][nt], a0, a1, a2, a3, b[nt][0], b[nt][1]);
            }
        }
    }
#pragma unroll
    for (int mt = 0; mt < 4; mt++) {
        int row = bm0 + m0 + mt * 16 + (lane >> 2);
#pragma unroll
        for (int nt = 0; nt < 4; nt++) {
            int col = n0 + nt * 8 + 2 * (lane & 3);
            if (row < n) {
                float2 c = *(float2*)&out[(size_t)row * 128 + col];
                c.x += 0.5f * acc[mt][nt][0];
                c.y += 0.5f * acc[mt][nt][1];
                *(float2*)&out[(size_t)row * 128 + col] = c;
            }
            if (row + 8 < n) {
                float2 c = *(float2*)&out[(size_t)(row + 8) * 128 + col];
                c.x += 0.5f * acc[mt][nt][2];
                c.y += 0.5f * acc[mt][nt][3];
                *(float2*)&out[(size_t)(row + 8) * 128 + col] = c;
            }
        }
    }
}

// ---------------- host orchestration ----------------
extern "C" void kernel_launch(void* const* d_in, const int* in_sizes, int n_in,
                              void* d_out, int out_size) {
    const float* x   = (const float*)d_in[0];
    const void*  ei  = d_in[1];
    const float* Wqw = (const float*)d_in[2];
    const float* Wqb = (const float*)d_in[3];
    const float* Wkw = (const float*)d_in[4];
    const float* Wkb = (const float*)d_in[5];
    const float* Wow = (const float*)d_in[6];
    const float* Wob = (const float*)d_in[7];
    float* out = (float*)d_out;

    int n = in_sizes[0] / CC;
    int E = in_sizes[1] / 2;

    void *pDeg, *pKvs, *pVs, *pKs, *pA16, *pB16;
    cudaGetSymbolAddress(&pDeg, g_deg);
    cudaGetSymbolAddress(&pKvs, g_kvs);
    cudaGetSymbolAddress(&pVs,  g_vssum);
    cudaGetSymbolAddress(&pKs,  g_kssum);
    cudaGetSymbolAddress(&pA16, g_tA16);
    cudaGetSymbolAddress(&pB16, g_tB16);

    static int smem_set = 0;
    if (!smem_set) {
        cudaFuncSetAttribute(iter_fused_kernel,
                             cudaFuncAttributeMaxDynamicSharedMemorySize,
                             SM_WORDS * 4);
        smem_set = 1;
    }

    // ---- edge prep ----
    cudaMemsetAsync(pDeg, 0, (size_t)n * sizeof(int));
    detect_dtype_kernel<<<1, 256>>>((const int*)ei, in_sizes[1]);
    edge_deg_kernel<<<(E + 255) / 256, 256>>>(ei, E);
    scan_kernel<<<1, 1024>>>(n, E);
    csr_scatter_kernel<<<(E + 255) / 256, 256>>>(ei, E);
    gcn_gather_x_kernel<<<(n * 32 + 255) / 256, 256>>>(x, (__nv_bfloat16*)pB16, n);

    dim3 gqk((n + 127) / 128, 4);
    qk_gemm_kernel<<<gqk, 256>>>(x, Wqw, Wqb, Wkw, Wkb, n);
    normalize_kernel<<<(n * 4 * 32 + 255) / 256, 256>>>(n);
    cudaMemsetAsync(pKs, 0, (size_t)HH * CC * sizeof(float));
    kssum_kernel<<<(n + 511) / 512, 256>>>(n);
    den_kernel<<<(n * 2 * 32 + 255) / 256, 256>>>(n);
    broadcast_kernel<<<(n * 256 + 255) / 256, 256>>>(x, n);
    out_init_kernel<<<(n + 127) / 128, 256>>>(x, Wow, Wob, out, n);

    // ---- K_ORDER iterations: kvs_reduce + fused(gather|attn|out) ----
    __nv_bfloat16* prev = (__nv_bfloat16*)pA16;
    __nv_bfloat16* nxt  = (__nv_bfloat16*)pB16;
    int nb = (n + 127) / 128;
    for (int ksl = 1; ksl <= 4; ksl++) {
        cudaMemsetAsync(pKvs, 0, (size_t)HH * CC * CC * sizeof(float));
        cudaMemsetAsync(pVs,  0, (size_t)HH * CC * sizeof(float));
        kvs_reduce_kernel<<<dim3((n + 1023) / 1024, 2), 256>>>(prev, n);
        iter_fused_kernel<<<nb, 256, SM_WORDS * 4>>>(prev, nxt, Wow, out, n, ksl,
                                                     (ksl == 1) ? 1 : 0);
        __nv_bfloat16* tmp = prev; prev = nxt; nxt = tmp;
    }
}